// round 9
// baseline (speedup 1.0000x reference)
#include <cuda_runtime.h>
#include <cstdint>

// CRF NLL: B=1024, L=512, T=50 (48 real tags + START(48) + STOP(49)).
// Active set is 48 tags: u[START]==0 after step0 (e_START = exp(logit-1e4) = 0),
// E[:,STOP]==0, and STOP's final weight trans[STOP][STOP]=-1e4 flushes in fp32.
#define TT        50
#define NACT      48
#define START_TAG 48
#define STOP_TAG  49
#define PADNEG    (-1e30f)

__device__ int   g_idx[1024];      // descending-length rank -> batch index
__device__ float g_partial[1024];  // per-batch (partition - gold)

// ---- packed f32x2 helpers -------------------------------------------------
static __device__ __forceinline__ void fma2(unsigned long long& acc,
                                            unsigned long long e,
                                            unsigned long long a) {
    asm("fma.rn.f32x2 %0, %1, %2, %0;" : "+l"(acc) : "l"(e), "l"(a));
}
static __device__ __forceinline__ unsigned long long add2(unsigned long long a,
                                                          unsigned long long b) {
    unsigned long long r;
    asm("add.rn.f32x2 %0, %1, %2;" : "=l"(r) : "l"(a), "l"(b));
    return r;
}
static __device__ __forceinline__ float2 u2f(unsigned long long v) {
    float2 r;
    asm("mov.b64 {%0,%1}, %2;" : "=f"(r.x), "=f"(r.y) : "l"(v));
    return r;
}
static __device__ __forceinline__ unsigned long long pack2(float lo, float hi) {
    unsigned long long v;
    asm("mov.b64 %0, {%1,%2};" : "=l"(v) : "f"(lo), "f"(hi));
    return v;
}
static __device__ __forceinline__ float rcp_fast(float x) {
    float r;
    asm("rcp.approx.f32 %0, %1;" : "=f"(r) : "f"(x));
    return r;
}

// ---------------------------------------------------------------------------
// Kernel 1: counting-sort scheduler (1 block, 1024 threads, ~2us).
// Histogram over length bins + Hillis-Steele scan + atomic scatter;
// writes g_idx[rank_desc] = b. Scatter order within equal-length bins is
// nondeterministic, but output determinism is unaffected: g_partial[b]
// depends only on b's data and the final reduction is index-ordered.
// ---------------------------------------------------------------------------
__global__ void crf_sched(const int* __restrict__ lens, int B) {
    __shared__ int hist[1024];
    __shared__ int scanbuf[1024];
    __shared__ int cnt[1024];
    const int t = threadIdx.x;

    if (B != 1024) {                     // fallback: identity schedule
        for (int i = t; i < B; i += 1024) g_idx[i] = i;
        return;
    }
    hist[t] = 0; cnt[t] = 0;
    __syncthreads();

    const int lb = lens[t] & 1023;       // lens in [1,512]
    atomicAdd(&hist[lb], 1);
    __syncthreads();

    // Hillis-Steele inclusive scan over 1024 bins (barriers unconditional)
    int v = hist[t];
    #pragma unroll
    for (int off = 1; off < 1024; off <<= 1) {
        scanbuf[t] = v;
        __syncthreads();
        if (t >= off) v += scanbuf[t - off];
        __syncthreads();
    }
    scanbuf[t] = v;                      // inclusive prefix
    __syncthreads();

    int start = scanbuf[lb] - hist[lb];  // exclusive prefix for own bin
    int pos = start + atomicAdd(&cnt[lb], 1);   // ascending-length position
    g_idx[1023 - pos] = t;               // descending rank -> batch
}

// ---------------------------------------------------------------------------
// One forward step (exp-domain, lagged reference-tag normalization).
// u broadcast via shfl.idx register rotation -- NO shared memory, NO syncwarp.
//   v_y = e_y * dot_y ; u_y' = v_y * r ; r = 1/v_0(prev step) ;
//   m += log(w) when the factor is applied  =>  alpha_y = m + log u_y.
// ---------------------------------------------------------------------------
static __device__ __forceinline__ void crf_step(
    float2 cur,
    const unsigned long long* __restrict__ E0,
    const unsigned long long* __restrict__ E1,
    float M0, float M1,
    float& u0, float& u1, float& m, float& r_cur, float& logw_cur)
{
    float e0 = __expf(cur.x + M0);       // off-chain (prefetched logit)
    float e1 = __expf(cur.y + M1);

    unsigned long long d0 = 0ull, d1 = 0ull, d2 = 0ull, d3 = 0ull;
    unsigned long long f0 = 0ull, f1 = 0ull, f2 = 0ull, f3 = 0ull;
    #pragma unroll
    for (int j = 0; j < 24; ++j) {
        float s0 = __shfl_sync(0xFFFFFFFFu, u0, j);   // u[2j]
        float s1 = __shfl_sync(0xFFFFFFFFu, u1, j);   // u[2j+1]
        unsigned long long a = pack2(s0, s1);
        switch (j & 3) {
            case 0: fma2(d0, E0[j], a); fma2(f0, E1[j], a); break;
            case 1: fma2(d1, E0[j], a); fma2(f1, E1[j], a); break;
            case 2: fma2(d2, E0[j], a); fma2(f2, E1[j], a); break;
            default: fma2(d3, E0[j], a); fma2(f3, E1[j], a); break;
        }
    }
    float2 sd = u2f(add2(add2(d0, d1), add2(d2, d3)));
    float dot0 = sd.x + sd.y;
    float2 sf = u2f(add2(add2(f0, f1), add2(f2, f3)));
    float dot1 = sf.x + sf.y;

    float v0 = e0 * dot0;
    float v1 = e1 * dot1;

    u0 = v0 * r_cur;                     // apply LAGGED factor from prev step
    u1 = v1 * r_cur;
    m += logw_cur;

    float w = __shfl_sync(0xFFFFFFFFu, v0, 0);
    r_cur    = rcp_fast(w);              // next step's factor (overlaps next FMAs)
    logw_cur = __logf(w);
}

// ---------------------------------------------------------------------------
// Process one sequence end-to-end; writes g_partial[b].
// ---------------------------------------------------------------------------
static __device__ __forceinline__ void crf_seq(
    int b, const float* __restrict__ logits, const float* __restrict__ trans,
    const int* __restrict__ labels, const int* __restrict__ lens, int L,
    int lane, int t0c,
    const unsigned long long* __restrict__ E0,
    const unsigned long long* __restrict__ E1,
    float M0, float M1, float tst0, float tst1, float ts0, float ts1)
{
    const int len = lens[b];
    const float* lg  = logits + (size_t)b * (size_t)L * TT;
    const int*   lab = labels + (size_t)b * L;

    // gold score (emission + transition), warp-parallel over l
    float acc = 0.0f;
    for (int l = lane; l < len; l += 32) {
        int cur = lab[l];
        acc += __ldg(&lg[l * TT + cur]);
        int prev = (l == 0) ? START_TAG : lab[l - 1];
        acc += __ldg(&trans[cur * TT + prev]);
    }
    if (lane == 0) acc += __ldg(&trans[STOP_TAG * TT + lab[len - 1]]);
    #pragma unroll
    for (int o = 16; o > 0; o >>= 1)
        acc += __shfl_xor_sync(0xFFFFFFFFu, acc, o);
    const float gold = acc;

    // step 0 closed form: alpha1[y] = logit0[y] + trans[y][START]
    float2 lgv = *(const float2*)&lg[t0c];
    float a0 = lgv.x + tst0;             // inactive lanes: -1e30 -> u = 0
    float a1 = lgv.y + tst1;

    float m  = __shfl_sync(0xFFFFFFFFu, a0, 0);
    float u0 = __expf(a0 - m);
    float u1 = __expf(a1 - m);

    float r_cur = 1.0f, logw_cur = 0.0f;

    // steps 1..len-1: unroll-4 main loop with depth-4 logit prefetch
    int l = 1;
    float2 q0, q1, q2, q3;
    if (len >= 9) {
        q0 = *(const float2*)&lg[1 * TT + t0c];
        q1 = *(const float2*)&lg[2 * TT + t0c];
        q2 = *(const float2*)&lg[3 * TT + t0c];
        q3 = *(const float2*)&lg[4 * TT + t0c];
        const float* pr = lg + 5 * TT + t0c;
        for (; l + 8 <= len; l += 4) {
            crf_step(q0, E0, E1, M0, M1, u0, u1, m, r_cur, logw_cur);
            q0 = *(const float2*)(pr);
            crf_step(q1, E0, E1, M0, M1, u0, u1, m, r_cur, logw_cur);
            q1 = *(const float2*)(pr + TT);
            crf_step(q2, E0, E1, M0, M1, u0, u1, m, r_cur, logw_cur);
            q2 = *(const float2*)(pr + 2 * TT);
            crf_step(q3, E0, E1, M0, M1, u0, u1, m, r_cur, logw_cur);
            q3 = *(const float2*)(pr + 3 * TT);
            pr += 4 * TT;
        }
    }
    for (; l < len; ++l) {
        float2 c = *(const float2*)&lg[l * TT + t0c];
        crf_step(c, E0, E1, M0, M1, u0, u1, m, r_cur, logw_cur);
    }

    // partition = m + LSE_y(log u_y + trans[STOP][y])
    float fv0 = __logf(u0) + ts0;
    float fv1 = __logf(u1) + ts1;
    float mx = fmaxf(fv0, fv1);
    #pragma unroll
    for (int o = 16; o > 0; o >>= 1)
        mx = fmaxf(mx, __shfl_xor_sync(0xFFFFFFFFu, mx, o));
    float ssum = __expf(fv0 - mx) + __expf(fv1 - mx);
    #pragma unroll
    for (int o = 16; o > 0; o >>= 1)
        ssum += __shfl_xor_sync(0xFFFFFFFFu, ssum, o);

    if (lane == 0) {
        float partition = m + mx + __logf(ssum);
        g_partial[b] = partition - gold;
    }
}

// ---------------------------------------------------------------------------
// Kernel 2: one warp per PAIR of sequences (rank w and rank B-1-w), serial.
// Every warp runs ~513 total steps -> balance independent of placement.
// ---------------------------------------------------------------------------
__global__ __launch_bounds__(32) void crf_main(
    const float* __restrict__ logits,
    const float* __restrict__ trans,
    const int*   __restrict__ labels,
    const int*   __restrict__ lens,
    int L, int B)
{
    const int w    = blockIdx.x;
    const int lane = threadIdx.x;

    const int bA = g_idx[w];
    const int bB = g_idx[B - 1 - w];

    // per-thread tag pair; build E rows from trans (L1-resident, 10KB)
    const int t0  = 2 * lane;
    const int t1  = t0 + 1;
    const int t0c = (t0 < NACT) ? t0 : NACT;
    const bool act = (t0 < NACT);

    float M0 = PADNEG, M1 = PADNEG;
    unsigned long long E0[24], E1[24];
    float tst0 = PADNEG, tst1 = PADNEG, ts0 = PADNEG, ts1 = PADNEG;

    if (act) {
        const float* r0 = trans + t0 * TT;
        const float* r1 = r0 + TT;
        #pragma unroll 8
        for (int x = 0; x < NACT; ++x) {
            M0 = fmaxf(M0, __ldg(&r0[x]));
            M1 = fmaxf(M1, __ldg(&r1[x]));
        }
        #pragma unroll
        for (int j = 0; j < 24; ++j) {
            E0[j] = pack2(__expf(__ldg(&r0[2 * j]) - M0),
                          __expf(__ldg(&r0[2 * j + 1]) - M0));
            E1[j] = pack2(__expf(__ldg(&r1[2 * j]) - M1),
                          __expf(__ldg(&r1[2 * j + 1]) - M1));
        }
        tst0 = __ldg(&r0[START_TAG]);
        tst1 = __ldg(&r1[START_TAG]);
        ts0  = __ldg(&trans[STOP_TAG * TT + t0]);
        ts1  = __ldg(&trans[STOP_TAG * TT + t1]);
    } else {
        #pragma unroll
        for (int j = 0; j < 24; ++j) { E0[j] = 0ull; E1[j] = 0ull; }
    }

    crf_seq(bA, logits, trans, labels, lens, L, lane, t0c,
            E0, E1, M0, M1, tst0, tst1, ts0, ts1);
    if (bB != bA)
        crf_seq(bB, logits, trans, labels, lens, L, lane, t0c,
                E0, E1, M0, M1, tst0, tst1, ts0, ts1);
}

// ---------------------------------------------------------------------------
// Kernel 3: deterministic final reduction -> scalar mean
// ---------------------------------------------------------------------------
__global__ void crf_reduce(float* __restrict__ out, int B) {
    __shared__ float s[256];
    float a = 0.0f;
    for (int i = threadIdx.x; i < B; i += 256) a += g_partial[i];
    s[threadIdx.x] = a;
    __syncthreads();
    #pragma unroll
    for (int st = 128; st > 0; st >>= 1) {
        if (threadIdx.x < st) s[threadIdx.x] += s[threadIdx.x + st];
        __syncthreads();
    }
    if (threadIdx.x == 0) out[0] = s[0] / (float)B;
}

// ---------------------------------------------------------------------------
extern "C" void kernel_launch(void* const* d_in, const int* in_sizes, int n_in,
                              void* d_out, int out_size)
{
    // Identify inputs by element count:
    //   logits 26,214,400 | labels 524,288 | transitions 2,500 | lens 1,024
    long long sz[8];
    for (int i = 0; i < n_in && i < 8; ++i) sz[i] = in_sizes[i];

    int i_logits = -1, i_trans = -1, i_labels = -1, i_lens = -1;
    long long mx = -1, mn = (long long)1 << 62;
    for (int i = 0; i < n_in; ++i) {
        if (sz[i] > mx) { mx = sz[i]; i_logits = i; }
        if (sz[i] < mn) { mn = sz[i]; i_lens = i; }
    }
    for (int i = 0; i < n_in; ++i) {
        if (i == i_logits || i == i_lens) continue;
        if (i_trans < 0) i_trans = i; else i_labels = i;
    }
    if (i_trans >= 0 && i_labels >= 0 && sz[i_trans] > sz[i_labels]) {
        int t = i_trans; i_trans = i_labels; i_labels = t;
    }

    const float* logits = (const float*)d_in[i_logits];
    const float* trans  = (const float*)d_in[i_trans];
    const int*   labels = (const int*)  d_in[i_labels];
    const int*   lens   = (const int*)  d_in[i_lens];
    int B = (int)sz[i_lens];
    int L = (int)(sz[i_labels] / B);

    int nwarps = (B + 1) / 2;

    crf_sched<<<1, 1024>>>(lens, B);
    crf_main<<<nwarps, 32>>>(logits, trans, labels, lens, L, B);
    crf_reduce<<<1, 256>>>((float*)d_out, B);
}